// round 1
// baseline (speedup 1.0000x reference)
#include <cuda_runtime.h>
#include <math.h>

// VanillaLSTM: B=64, CH=2 -> R=128 independent rows; H=768; 256 steps.
// Per step: g[128,3072] = h[128,768] @ Wh[768,3072] + x_t*w0 + b, then LSTM update.
// Strategy (R0): fp32 SIMT GEMM using packed fma.rn.f32x2 (FFMA2) over k-pairs.
//   - weights repacked once per replay into [jb][k2][c] float2 (k,k+1) layout
//   - block = 64 rows x 32 g-cols (8 j-cols x 4 gates), grid (96,2) = 192 blocks
//   - thread = 8 rows x 2 g-cols, acc in f32x2 over k, halves summed at end
//   - elementwise LSTM fused: lanes p and p^1 hold (i,f) and (chat,o) of same j,
//     exchanged with __shfl_xor_sync(...,1)

#define ROWS 128
#define HDIM 768
#define SEQ  256
#define KC   64     // k elements per smem chunk
#define NJB  96     // 768/8 j-column groups

__device__ __align__(16) float  g_h[2][ROWS * HDIM];
__device__ __align__(16) float  g_c[ROWS * HDIM];
__device__ __align__(16) float2 g_wpk[NJB * 384 * 32];  // [jb][k2][c], (W[2k2+1..2], cols)
__device__ __align__(16) float2 g_wxb[NJB * 32];        // per col: (W_row0, bias)

__device__ __forceinline__ unsigned long long f2u(float2 v) {
    unsigned long long r;
    asm("mov.b64 %0, {%1,%2};" : "=l"(r) : "f"(v.x), "f"(v.y));
    return r;
}
__device__ __forceinline__ float2 u2f(unsigned long long u) {
    float2 v;
    asm("mov.b64 {%0,%1}, %2;" : "=f"(v.x), "=f"(v.y) : "l"(u));
    return v;
}
__device__ __forceinline__ unsigned long long ffma2(unsigned long long a,
                                                    unsigned long long b,
                                                    unsigned long long c) {
    unsigned long long d;
    asm("fma.rn.f32x2 %0, %1, %2, %3;" : "=l"(d) : "l"(a), "l"(b), "l"(c));
    return d;
}

// ---------------------------------------------------------------------------
// Init: copy h0 -> g_h[0], c0 -> g_c (must run inside the graph every replay)
// ---------------------------------------------------------------------------
__global__ void init_state(const float* __restrict__ h0, const float* __restrict__ c0) {
    int i = blockIdx.x * 256 + threadIdx.x;
    if (i < ROWS * HDIM) {
        g_h[0][i] = h0[i];
        g_c[i]    = c0[i];
    }
}

// ---------------------------------------------------------------------------
// Repack weights: g_wpk[jb*12288 + k2*32 + c] = (Wg[1+2k2][j], Wg[2+2k2][j])
// with c = jj*4 + gate, j = jb*8 + jj.   Also g_wxb[jb*32+c] = (Wg[0][j], b[j]).
// ---------------------------------------------------------------------------
__global__ void repack(const float* __restrict__ Wi, const float* __restrict__ Wf,
                       const float* __restrict__ Wc, const float* __restrict__ Wo,
                       const float* __restrict__ bi, const float* __restrict__ bf,
                       const float* __restrict__ bc, const float* __restrict__ bo) {
    int idx = blockIdx.x * 256 + threadIdx.x;
    const int TOT = NJB * 384 * 32;
    if (idx < TOT) {
        int c  = idx & 31;
        int k2 = (idx >> 5) % 384;
        int jb = (idx >> 5) / 384;
        int gate = c & 3;
        int j = jb * 8 + (c >> 2);
        const float* W = (gate == 0) ? Wi : (gate == 1) ? Wf : (gate == 2) ? Wc : Wo;
        g_wpk[idx] = make_float2(W[(1 + 2 * k2) * HDIM + j],
                                 W[(2 + 2 * k2) * HDIM + j]);
    }
    if (idx < NJB * 32) {
        int c  = idx & 31;
        int jb = idx >> 5;
        int gate = c & 3;
        int j = jb * 8 + (c >> 2);
        const float* W = (gate == 0) ? Wi : (gate == 1) ? Wf : (gate == 2) ? Wc : Wo;
        const float* B = (gate == 0) ? bi : (gate == 1) ? bf : (gate == 2) ? bc : bo;
        g_wxb[idx] = make_float2(W[j], B[j]);
    }
}

// ---------------------------------------------------------------------------
// One LSTM step. grid (96, 2): jb = blockIdx.x (8 j-cols), rb = blockIdx.y (64 rows).
// 128 threads: rg = tid>>4 (8 row-groups of 8 rows), p = tid&15 (2 g-cols each).
// ---------------------------------------------------------------------------
__global__ __launch_bounds__(128) void lstm_step(const float* __restrict__ x,
                                                 int t, int par) {
    __shared__ __align__(16) unsigned long long hs2[KC / 2][67];  // [k2][row] padded
    __shared__ __align__(16) unsigned long long ws[KC / 2][32];   // [k2][col]
    __shared__ float xs[64];

    const int tid = threadIdx.x;
    const int jb = blockIdx.x, rb = blockIdx.y;
    const int rg = tid >> 4, p = tid & 15;

    const float* __restrict__ h_in  = g_h[par];
    float* __restrict__       h_out = g_h[par ^ 1];

    if (tid < 64) {
        int r = rb * 64 + tid;
        xs[tid] = x[(r >> 1) * 512 + 2 * t + (r & 1)];
    }

    unsigned long long acc[8][2];
#pragma unroll
    for (int i = 0; i < 8; i++) { acc[i][0] = 0ull; acc[i][1] = 0ull; }

    const float2* __restrict__ wsrc = g_wpk + jb * (384 * 32);

    for (int kc = 0; kc < HDIM / KC; ++kc) {
        __syncthreads();
        // stage weight chunk: (KC/2)*32 = 1024 float2 = 512 float4
        {
            const float4* w4 = (const float4*)(wsrc + kc * (KC / 2) * 32);
            float4* s4 = (float4*)ws;
#pragma unroll
            for (int u = 0; u < 4; ++u) s4[tid + 128 * u] = w4[tid + 128 * u];
        }
        // stage h chunk: 64 rows x KC floats, packed into k-pairs
#pragma unroll
        for (int u = 0; u < 8; ++u) {
            int idx = tid + 128 * u;     // 0..1023
            int r  = idx >> 4;
            int k4 = idx & 15;
            float4 v = *(const float4*)&h_in[(rb * 64 + r) * HDIM + kc * KC + k4 * 4];
            hs2[k4 * 2][r]     = f2u(make_float2(v.x, v.y));
            hs2[k4 * 2 + 1][r] = f2u(make_float2(v.z, v.w));
        }
        __syncthreads();

#pragma unroll 4
        for (int k2 = 0; k2 < KC / 2; ++k2) {
            unsigned long long w0 = ws[k2][2 * p];
            unsigned long long w1 = ws[k2][2 * p + 1];
#pragma unroll
            for (int i = 0; i < 8; i++) {
                unsigned long long h2 = hs2[k2][rg * 8 + i];
                acc[i][0] = ffma2(h2, w0, acc[i][0]);
                acc[i][1] = ffma2(h2, w1, acc[i][1]);
            }
        }
    }

    // epilogue: add x/bias terms, exchange gate pairs, LSTM update
    const float2 xb0 = g_wxb[jb * 32 + 2 * p];
    const float2 xb1 = g_wxb[jb * 32 + 2 * p + 1];
    const int j = jb * 8 + (p >> 1);

#pragma unroll
    for (int i = 0; i < 8; i++) {
        int rl = rg * 8 + i;
        int r  = rb * 64 + rl;
        float2 a0 = u2f(acc[i][0]);
        float2 a1 = u2f(acc[i][1]);
        float xt = xs[rl];
        float pre0 = a0.x + a0.y + xt * xb0.x + xb0.y;
        float pre1 = a1.x + a1.y + xt * xb1.x + xb1.y;
        // even p holds (pre_i, pre_f); odd p holds (pre_chat, pre_o)
        float q0 = __shfl_xor_sync(0xffffffffu, pre0, 1);
        float q1 = __shfl_xor_sync(0xffffffffu, pre1, 1);
        if ((p & 1) == 0) {
            float cold = g_c[r * HDIM + j];
            float ig = 1.f / (1.f + expf(-pre0));
            float fg = 1.f / (1.f + expf(-pre1));
            float cn = fg * cold + ig * tanhf(q0);
            float hn = q1 * tanhf(cn);   // NOTE: no sigmoid on output gate
            g_c[r * HDIM + j]   = cn;
            h_out[r * HDIM + j] = hn;
        }
    }
}

// ---------------------------------------------------------------------------
// Final projection: out[r] = dot(h_T[r,:], W_out) + b_out. 128 warps, 1 per row.
// ---------------------------------------------------------------------------
__global__ void out_final(const float* __restrict__ Wout,
                          const float* __restrict__ bout,
                          float* __restrict__ out) {
    int gtid = blockIdx.x * 128 + threadIdx.x;
    int r = gtid >> 5, lane = gtid & 31;
    float s = 0.f;
    for (int k = lane; k < HDIM; k += 32) s += g_h[0][r * HDIM + k] * Wout[k];
#pragma unroll
    for (int o = 16; o; o >>= 1) s += __shfl_xor_sync(0xffffffffu, s, o);
    if (lane == 0) out[r] = s + bout[0];
}

// ---------------------------------------------------------------------------
extern "C" void kernel_launch(void* const* d_in, const int* in_sizes, int n_in,
                              void* d_out, int out_size) {
    (void)in_sizes; (void)n_in; (void)out_size;
    const float* x    = (const float*)d_in[0];
    const float* h0   = (const float*)d_in[1];
    const float* c0   = (const float*)d_in[2];
    const float* Wi   = (const float*)d_in[3];
    const float* bi   = (const float*)d_in[4];
    const float* Wf   = (const float*)d_in[5];
    const float* bf   = (const float*)d_in[6];
    const float* Wc   = (const float*)d_in[7];
    const float* bc   = (const float*)d_in[8];
    const float* Wo   = (const float*)d_in[9];
    const float* bo   = (const float*)d_in[10];
    const float* Wout = (const float*)d_in[11];
    const float* bout = (const float*)d_in[12];
    float* out = (float*)d_out;

    init_state<<<(ROWS * HDIM + 255) / 256, 256>>>(h0, c0);
    repack<<<(NJB * 384 * 32 + 255) / 256, 256>>>(Wi, Wf, Wc, Wo, bi, bf, bc, bo);

    dim3 grid(NJB, 2);
    for (int t = 0; t < SEQ; ++t) {
        lstm_step<<<grid, 128>>>(x, t, t & 1);
    }
    out_final<<<32, 128>>>(Wout, bout, out);
}

// round 3
// speedup vs baseline: 1.5900x; 1.5900x over previous
#include <cuda_runtime.h>
#include <cuda_bf16.h>
#include <math.h>
#include <stdint.h>

// VanillaLSTM on sm_103 via mma.sync bf16 (HMMA). R=128 rows, H=768, 256 steps.
// Per step: g[128,3072] = h@Wg + x*w0 + b, fused LSTM update.
// bf16-split: h=h_hi+h_lo, W=W_hi+W_lo; 3 MMAs (hi*hi, hi*lo, lo*hi), fp32 acc.
// 96 CTAs x 32 gate-cols (8 j x 4 gates interleaved), 256 threads (8 warps x 16 rows).

#define ROWS 128
#define HDIM 768
#define SEQ  256
#define NCTA 96
#define NCHUNK 12

#define APITCH 144          // 72 bf16 per padded row
#define A_HI 0
#define A_LO 18432          // 128*144
#define B_HI 36864
#define B_LO 41472          // +32*144
#define BUFSZ 46080
#define SMEM_TOTAL (2 * BUFSZ)   // 92160

__device__ __align__(16) __nv_bfloat16 g_hhi[2][ROWS * HDIM];
__device__ __align__(16) __nv_bfloat16 g_hlo[2][ROWS * HDIM];
__device__ __align__(16) float         g_c[ROWS * HDIM];
// repacked weights: [(nb*12+kc)*2048 + n*64 + kl], n = jl*4+gate (32 per CTA)
__device__ __align__(16) __nv_bfloat16 g_Bhi[NCTA * NCHUNK * 2048];
__device__ __align__(16) __nv_bfloat16 g_Blo[NCTA * NCHUNK * 2048];
__device__ __align__(16) float2        g_wxb[NCTA * 32];   // (W_row0, bias) per col

// ---------------------------------------------------------------------------
__device__ __forceinline__ uint32_t smem_u32(const void* p) {
    uint32_t a;
    asm("{ .reg .u64 t; cvta.to.shared.u64 t, %1; cvt.u32.u64 %0, t; }" : "=r"(a) : "l"(p));
    return a;
}
__device__ __forceinline__ void cpa16(uint32_t dst, const void* src) {
    asm volatile("cp.async.cg.shared.global [%0], [%1], 16;" :: "r"(dst), "l"(src) : "memory");
}
__device__ __forceinline__ void cp_commit() {
    asm volatile("cp.async.commit_group;" ::: "memory");
}
__device__ __forceinline__ void cp_wait1() {
    asm volatile("cp.async.wait_group 1;" ::: "memory");
}
__device__ __forceinline__ void cp_wait0() {
    asm volatile("cp.async.wait_group 0;" ::: "memory");
}
__device__ __forceinline__ void ldsm4(uint32_t* r, uint32_t addr) {
    asm volatile("ldmatrix.sync.aligned.m8n8.x4.shared.b16 {%0,%1,%2,%3}, [%4];"
                 : "=r"(r[0]), "=r"(r[1]), "=r"(r[2]), "=r"(r[3]) : "r"(addr));
}
__device__ __forceinline__ void mma_bf16(float* d, const uint32_t* a, uint32_t b0, uint32_t b1) {
    asm volatile(
        "mma.sync.aligned.m16n8k16.row.col.f32.bf16.bf16.f32 "
        "{%0,%1,%2,%3}, {%4,%5,%6,%7}, {%8,%9}, {%0,%1,%2,%3};"
        : "+f"(d[0]), "+f"(d[1]), "+f"(d[2]), "+f"(d[3])
        : "r"(a[0]), "r"(a[1]), "r"(a[2]), "r"(a[3]), "r"(b0), "r"(b1));
}

// ---------------------------------------------------------------------------
__global__ void init_state(const float* __restrict__ h0, const float* __restrict__ c0) {
    int i = blockIdx.x * 256 + threadIdx.x;
    if (i < ROWS * HDIM) {
        float v = h0[i];
        __nv_bfloat16 hi = __float2bfloat16(v);
        g_hhi[0][i] = hi;
        g_hlo[0][i] = __float2bfloat16(v - __bfloat162float(hi));
        g_c[i] = c0[i];
    }
}

// ---------------------------------------------------------------------------
__global__ void repack(const float* __restrict__ Wi, const float* __restrict__ Wf,
                       const float* __restrict__ Wc, const float* __restrict__ Wo,
                       const float* __restrict__ bi, const float* __restrict__ bf,
                       const float* __restrict__ bc, const float* __restrict__ bo) {
    int idx = blockIdx.x * 256 + threadIdx.x;
    const int TOT = NCTA * NCHUNK * 2048;
    if (idx < TOT) {
        int kl  = idx & 63;
        int n   = (idx >> 6) & 31;
        int blk = idx >> 11;
        int kc  = blk % NCHUNK;
        int nb  = blk / NCHUNK;
        int gate = n & 3;
        int j = nb * 8 + (n >> 2);
        const float* W = (gate == 0) ? Wi : (gate == 1) ? Wf : (gate == 2) ? Wc : Wo;
        float v = W[(1 + kc * 64 + kl) * HDIM + j];
        __nv_bfloat16 hi = __float2bfloat16(v);
        g_Bhi[idx] = hi;
        g_Blo[idx] = __float2bfloat16(v - __bfloat162float(hi));
    }
    if (idx < NCTA * 32) {
        int n = idx & 31;
        int nb = idx >> 5;
        int gate = n & 3;
        int j = nb * 8 + (n >> 2);
        const float* W = (gate == 0) ? Wi : (gate == 1) ? Wf : (gate == 2) ? Wc : Wo;
        const float* B = (gate == 0) ? bi : (gate == 1) ? bf : (gate == 2) ? bc : bo;
        g_wxb[idx] = make_float2(W[j], B[j]);
    }
}

// ---------------------------------------------------------------------------
// One LSTM step. 96 CTAs x 256 threads. Warp w owns rows [w*16, w*16+16).
__global__ void __launch_bounds__(256, 1) lstm_step_hmma(const float* __restrict__ x,
                                                         int t, int par) {
    extern __shared__ char smem[];
    const uint32_t sb = smem_u32(smem);
    const int tid = threadIdx.x;
    const int lane = tid & 31, wid = tid >> 5;
    const int nb = blockIdx.x;

    const __nv_bfloat16* __restrict__ hhi = g_hhi[par];
    const __nv_bfloat16* __restrict__ hlo = g_hlo[par];
    const __nv_bfloat16* __restrict__ bhi = g_Bhi + nb * (NCHUNK * 2048);
    const __nv_bfloat16* __restrict__ blo = g_Blo + nb * (NCHUNK * 2048);

    // staging slices for this thread
    const int arow0 = tid >> 3, ach = tid & 7;   // +32 rows per u-iter
    const int bn = tid >> 3, bch = tid & 7;

    // ldmatrix lane offsets
    const int sel = lane >> 3, li = lane & 7;
    const uint32_t aoff = (uint32_t)((wid * 16 + li + (sel & 1) * 8) * APITCH + (sel >> 1) * 16);
    const uint32_t boff = (uint32_t)((li + (sel >> 1) * 8) * APITCH + (sel & 1) * 16);

    float d[4][4];
#pragma unroll
    for (int i = 0; i < 4; i++)
#pragma unroll
        for (int k = 0; k < 4; k++) d[i][k] = 0.f;

    // issue chunk c into buffer b
    auto issue = [&](int c, int b) {
        const uint32_t bufs = sb + b * BUFSZ;
#pragma unroll
        for (int u = 0; u < 4; ++u) {
            int row = arow0 + 32 * u;
            uint32_t doff = (uint32_t)(row * APITCH + ach * 16);
            const int so = row * HDIM + c * 64 + ach * 8;
            cpa16(bufs + A_HI + doff, hhi + so);
            cpa16(bufs + A_LO + doff, hlo + so);
        }
        {
            uint32_t doff = (uint32_t)(bn * APITCH + bch * 16);
            const int so = c * 2048 + bn * 64 + bch * 8;
            cpa16(bufs + B_HI + doff, bhi + so);
            cpa16(bufs + B_LO + doff, blo + so);
        }
        cp_commit();
    };

    issue(0, 0);
    issue(1, 1);

    for (int c = 0; c < NCHUNK; ++c) {
        if (c < NCHUNK - 1) cp_wait1(); else cp_wait0();
        __syncthreads();
        const uint32_t bufs = sb + (c & 1) * BUFSZ;
#pragma unroll
        for (int ks = 0; ks < 4; ++ks) {
            const uint32_t ka = bufs + ks * 32;
            uint32_t ah[4], al[4];
            ldsm4(ah, ka + A_HI + aoff);
            ldsm4(al, ka + A_LO + aoff);
#pragma unroll
            for (int p = 0; p < 2; ++p) {
                uint32_t bh[4], bl[4];
                const uint32_t bb = ka + boff + p * (16 * APITCH);
                ldsm4(bh, bb + B_HI);
                ldsm4(bl, bb + B_LO);
                mma_bf16(d[2 * p],     ah, bh[0], bh[1]);
                mma_bf16(d[2 * p],     ah, bl[0], bl[1]);
                mma_bf16(d[2 * p],     al, bh[0], bh[1]);
                mma_bf16(d[2 * p + 1], ah, bh[2], bh[3]);
                mma_bf16(d[2 * p + 1], ah, bl[2], bl[3]);
                mma_bf16(d[2 * p + 1], al, bh[2], bh[3]);
            }
        }
        __syncthreads();
        if (c + 2 < NCHUNK) issue(c + 2, c & 1);
    }

    // ---------------- fused LSTM epilogue ----------------
    // thread handles one row: even lane -> r, odd lane -> r+8
    const int r_even = wid * 16 + (lane >> 2);
    const int my_row = r_even + (lane & 1) * 8;
    const float xv = x[(my_row >> 1) * 512 + 2 * t + (my_row & 1)];
    __nv_bfloat16* __restrict__ ohi = g_hhi[par ^ 1];
    __nv_bfloat16* __restrict__ olo = g_hlo[par ^ 1];

#pragma unroll
    for (int nt = 0; nt < 4; ++nt) {
        const int jl = nt * 2 + ((lane & 3) >> 1);
        float p0 = __shfl_xor_sync(0xffffffffu, d[nt][0], 1);
        float p1 = __shfl_xor_sync(0xffffffffu, d[nt][1], 1);
        float p2 = __shfl_xor_sync(0xffffffffu, d[nt][2], 1);
        float p3 = __shfl_xor_sync(0xffffffffu, d[nt][3], 1);
        float gi, gf, gc, go;
        if (!(lane & 1)) { gi = d[nt][0]; gf = d[nt][1]; gc = p0; go = p1; }
        else             { gi = p2;       gf = p3;       gc = d[nt][2]; go = d[nt][3]; }
        const float2* __restrict__ wxb = g_wxb + nb * 32 + 4 * jl;
        float2 wi = wxb[0], wf = wxb[1], wc = wxb[2], wo = wxb[3];
        float pi = gi + xv * wi.x + wi.y;
        float pf = gf + xv * wf.x + wf.y;
        float pc = gc + xv * wc.x + wc.y;
        float po = go + xv * wo.x + wo.y;
        const int idx = my_row * HDIM + nb * 8 + jl;
        float cold = g_c[idx];
        float ig = 1.f / (1.f + expf(-pi));
        float fg = 1.f / (1.f + expf(-pf));
        float cn = fg * cold + ig * tanhf(pc);
        float hn = po * tanhf(cn);   // no sigmoid on output gate
        g_c[idx] = cn;
        __nv_bfloat16 hi = __float2bfloat16(hn);
        ohi[idx] = hi;
        olo[idx] = __float2bfloat16(hn - __bfloat162float(hi));
    }
}

// ---------------------------------------------------------------------------
__global__ void out_final(const float* __restrict__ Wout,
                          const float* __restrict__ bout,
                          float* __restrict__ out) {
    int gtid = blockIdx.x * 128 + threadIdx.x;
    int r = gtid >> 5, lane = gtid & 31;
    float s = 0.f;
    for (int k = lane; k < HDIM; k += 32) {
        float h = __bfloat162float(g_hhi[0][r * HDIM + k]) +
                  __bfloat162float(g_hlo[0][r * HDIM + k]);
        s += h * Wout[k];
    }
#pragma unroll
    for (int o = 16; o; o >>= 1) s += __shfl_xor_sync(0xffffffffu, s, o);
    if (lane == 0) out[r] = s + bout[0];
}

// ---------------------------------------------------------------------------
extern "C" void kernel_launch(void* const* d_in, const int* in_sizes, int n_in,
                              void* d_out, int out_size) {
    (void)in_sizes; (void)n_in; (void)out_size;
    const float* x    = (const float*)d_in[0];
    const float* h0   = (const float*)d_in[1];
    const float* c0   = (const float*)d_in[2];
    const float* Wi   = (const float*)d_in[3];
    const float* bi   = (const float*)d_in[4];
    const float* Wf   = (const float*)d_in[5];
    const float* bf   = (const float*)d_in[6];
    const float* Wc   = (const float*)d_in[7];
    const float* bc   = (const float*)d_in[8];
    const float* Wo   = (const float*)d_in[9];
    const float* bo   = (const float*)d_in[10];
    const float* Wout = (const float*)d_in[11];
    const float* bout = (const float*)d_in[12];
    float* out = (float*)d_out;

    static int configured = 0;
    if (!configured) {
        cudaFuncSetAttribute(lstm_step_hmma,
                             cudaFuncAttributeMaxDynamicSharedMemorySize, SMEM_TOTAL);
        configured = 1;
    }

    init_state<<<(ROWS * HDIM + 255) / 256, 256>>>(h0, c0);
    repack<<<(NCTA * NCHUNK * 2048 + 255) / 256, 256>>>(Wi, Wf, Wc, Wo, bi, bf, bc, bo);

    for (int t = 0; t < SEQ; ++t) {
        lstm_step_hmma<<<NCTA, 256, SMEM_TOTAL>>>(x, t, t & 1);
    }
    out_final<<<32, 128>>>(Wout, bout, out);
}

// round 4
// speedup vs baseline: 2.4302x; 1.5285x over previous
#include <cuda_runtime.h>
#include <cuda_bf16.h>
#include <math.h>
#include <stdint.h>

// VanillaLSTM persistent kernel (sm_103 HMMA bf16-split).
// 96 CTAs x 256 threads, 1 CTA/SM, all 256 steps inside one kernel.
// Weights resident in SMEM (hi+lo, ldmatrix pitch-144 layout).
// Per step: stream h (double-buffered cp.async), 3-MMA bf16-split GEMM,
// fused LSTM epilogue, gpu-scope grid sync.

#define ROWS 128
#define HDIM 768
#define SEQ  256
#define NCTA 96
#define NCHUNK 12
#define APITCH 144

// smem layout (bytes)
#define WS_HI 0
#define WS_LO 55296              // 12 chunks * 32 rows * 144
#define A_BASE 110592
#define ABUF 36864               // one buffer: hi(18432) + lo(18432)
#define A_HI 0
#define A_LO 18432
#define SMEM_TOTAL (A_BASE + 2 * ABUF)   // 184320

__device__ __align__(16) __nv_bfloat16 g_hhi[2][ROWS * HDIM];
__device__ __align__(16) __nv_bfloat16 g_hlo[2][ROWS * HDIM];
__device__ __align__(16) float         g_c[ROWS * HDIM];
__device__ __align__(16) __nv_bfloat16 g_Bhi[NCTA * NCHUNK * 2048];
__device__ __align__(16) __nv_bfloat16 g_Blo[NCTA * NCHUNK * 2048];
__device__ __align__(16) float2        g_wxb[NCTA * 32];
__device__ unsigned g_sync_ctr;

// ---------------------------------------------------------------------------
__device__ __forceinline__ uint32_t smem_u32(const void* p) {
    uint32_t a;
    asm("{ .reg .u64 t; cvta.to.shared.u64 t, %1; cvt.u32.u64 %0, t; }" : "=r"(a) : "l"(p));
    return a;
}
__device__ __forceinline__ void cpa16(uint32_t dst, const void* src) {
    asm volatile("cp.async.cg.shared.global [%0], [%1], 16;" :: "r"(dst), "l"(src) : "memory");
}
__device__ __forceinline__ void cp_commit() {
    asm volatile("cp.async.commit_group;" ::: "memory");
}
__device__ __forceinline__ void cp_wait1() {
    asm volatile("cp.async.wait_group 1;" ::: "memory");
}
__device__ __forceinline__ void cp_wait0() {
    asm volatile("cp.async.wait_group 0;" ::: "memory");
}
__device__ __forceinline__ void ldsm4(uint32_t* r, uint32_t addr) {
    asm volatile("ldmatrix.sync.aligned.m8n8.x4.shared.b16 {%0,%1,%2,%3}, [%4];"
                 : "=r"(r[0]), "=r"(r[1]), "=r"(r[2]), "=r"(r[3]) : "r"(addr));
}
__device__ __forceinline__ void mma_bf16(float* d, const uint32_t* a, uint32_t b0, uint32_t b1) {
    asm volatile(
        "mma.sync.aligned.m16n8k16.row.col.f32.bf16.bf16.f32 "
        "{%0,%1,%2,%3}, {%4,%5,%6,%7}, {%8,%9}, {%0,%1,%2,%3};"
        : "+f"(d[0]), "+f"(d[1]), "+f"(d[2]), "+f"(d[3])
        : "r"(a[0]), "r"(a[1]), "r"(a[2]), "r"(a[3]), "r"(b0), "r"(b1));
}

// ---------------------------------------------------------------------------
__global__ void init_state(const float* __restrict__ h0, const float* __restrict__ c0) {
    int i = blockIdx.x * 256 + threadIdx.x;
    if (i == 0) g_sync_ctr = 0u;
    if (i < ROWS * HDIM) {
        float v = h0[i];
        __nv_bfloat16 hi = __float2bfloat16(v);
        g_hhi[0][i] = hi;
        g_hlo[0][i] = __float2bfloat16(v - __bfloat162float(hi));
        g_c[i] = c0[i];
    }
}

// ---------------------------------------------------------------------------
__global__ void repack(const float* __restrict__ Wi, const float* __restrict__ Wf,
                       const float* __restrict__ Wc, const float* __restrict__ Wo,
                       const float* __restrict__ bi, const float* __restrict__ bf,
                       const float* __restrict__ bc, const float* __restrict__ bo) {
    int idx = blockIdx.x * 256 + threadIdx.x;
    const int TOT = NCTA * NCHUNK * 2048;
    if (idx < TOT) {
        int kl  = idx & 63;
        int n   = (idx >> 6) & 31;
        int blk = idx >> 11;
        int kc  = blk % NCHUNK;
        int nb  = blk / NCHUNK;
        int gate = n & 3;
        int j = nb * 8 + (n >> 2);
        const float* W = (gate == 0) ? Wi : (gate == 1) ? Wf : (gate == 2) ? Wc : Wo;
        float v = W[(1 + kc * 64 + kl) * HDIM + j];
        __nv_bfloat16 hi = __float2bfloat16(v);
        g_Bhi[idx] = hi;
        g_Blo[idx] = __float2bfloat16(v - __bfloat162float(hi));
    }
    if (idx < NCTA * 32) {
        int n = idx & 31;
        int nb = idx >> 5;
        int gate = n & 3;
        int j = nb * 8 + (n >> 2);
        const float* W = (gate == 0) ? Wi : (gate == 1) ? Wf : (gate == 2) ? Wc : Wo;
        const float* B = (gate == 0) ? bi : (gate == 1) ? bf : (gate == 2) ? bc : bo;
        g_wxb[idx] = make_float2(W[j], B[j]);
    }
}

// ---------------------------------------------------------------------------
__global__ void __launch_bounds__(256, 1) lstm_persistent(const float* __restrict__ x) {
    extern __shared__ char smem[];
    const uint32_t sb = smem_u32(smem);
    const int tid = threadIdx.x;
    const int lane = tid & 31, wid = tid >> 5;
    const int nb = blockIdx.x;

    // ---------------- prologue: stage W into smem (once) ----------------
    {
        const uint4* __restrict__ sh = ((const uint4*)g_Bhi) + nb * (NCHUNK * 256);
        const uint4* __restrict__ sl = ((const uint4*)g_Blo) + nb * (NCHUNK * 256);
        for (int i = tid; i < NCHUNK * 256; i += 256) {
            int c = i >> 8, r = i & 255;
            int n = r >> 3, k8 = r & 7;
            uint32_t off = (uint32_t)(c * 4608 + n * APITCH + k8 * 16);
            *(uint4*)(smem + WS_HI + off) = sh[i];
            *(uint4*)(smem + WS_LO + off) = sl[i];
        }
    }
    __syncthreads();

    // per-thread staging slices
    const int arow0 = tid >> 3, ach = tid & 7;

    // ldmatrix lane offsets
    const int sel = lane >> 3, li = lane & 7;
    const uint32_t aoff = (uint32_t)((wid * 16 + li + (sel & 1) * 8) * APITCH + (sel >> 1) * 16);
    const uint32_t boff = (uint32_t)((li + (sel >> 1) * 8) * APITCH + (sel & 1) * 16);

    // epilogue constants
    const int my_row = wid * 16 + (lane >> 2) + (lane & 1) * 8;
    const float* __restrict__ xrow = x + (my_row >> 1) * 512 + (my_row & 1);
    const float2* __restrict__ wxbp = g_wxb + nb * 32;

    for (int t = 0; t < SEQ; ++t) {
        const int par = t & 1;
        const __nv_bfloat16* __restrict__ hhi = g_hhi[par];
        const __nv_bfloat16* __restrict__ hlo = g_hlo[par];
        __nv_bfloat16* __restrict__ ohi = g_hhi[par ^ 1];
        __nv_bfloat16* __restrict__ olo = g_hlo[par ^ 1];

        float d[4][4];
#pragma unroll
        for (int i = 0; i < 4; i++)
#pragma unroll
            for (int k = 0; k < 4; k++) d[i][k] = 0.f;

        // issue A chunk c into buffer b
        auto issue = [&](int c, int b) {
            const uint32_t bufs = sb + A_BASE + b * ABUF;
#pragma unroll
            for (int u = 0; u < 4; ++u) {
                int row = arow0 + 32 * u;
                uint32_t doff = (uint32_t)(row * APITCH + ach * 16);
                const int so = row * HDIM + c * 64 + ach * 8;
                cpa16(bufs + A_HI + doff, hhi + so);
                cpa16(bufs + A_LO + doff, hlo + so);
            }
            cp_commit();
        };

        issue(0, 0);
        issue(1, 1);

        for (int c = 0; c < NCHUNK; ++c) {
            if (c < NCHUNK - 1) cp_wait1(); else cp_wait0();
            __syncthreads();
            const uint32_t abuf = sb + A_BASE + (c & 1) * ABUF;
            const uint32_t wbase = sb + (uint32_t)(c * 4608);
#pragma unroll
            for (int ks = 0; ks < 4; ++ks) {
                uint32_t ah[4], al[4];
                ldsm4(ah, abuf + A_HI + aoff + ks * 32);
                ldsm4(al, abuf + A_LO + aoff + ks * 32);
#pragma unroll
                for (int p = 0; p < 2; ++p) {
                    uint32_t bh[4], bl[4];
                    const uint32_t bb = wbase + boff + ks * 32 + p * (16 * APITCH);
                    ldsm4(bh, bb + WS_HI);
                    ldsm4(bl, bb + WS_LO);
                    mma_bf16(d[2 * p],     ah, bh[0], bh[1]);
                    mma_bf16(d[2 * p],     ah, bl[0], bl[1]);
                    mma_bf16(d[2 * p],     al, bh[0], bh[1]);
                    mma_bf16(d[2 * p + 1], ah, bh[2], bh[3]);
                    mma_bf16(d[2 * p + 1], ah, bl[2], bl[3]);
                    mma_bf16(d[2 * p + 1], al, bh[2], bh[3]);
                }
            }
            __syncthreads();
            if (c + 2 < NCHUNK) issue(c + 2, c & 1);
        }

        // ---------------- fused LSTM epilogue ----------------
        const float xv = xrow[2 * t];
#pragma unroll
        for (int nt = 0; nt < 4; ++nt) {
            const int jl = nt * 2 + ((lane & 3) >> 1);
            float p0 = __shfl_xor_sync(0xffffffffu, d[nt][0], 1);
            float p1 = __shfl_xor_sync(0xffffffffu, d[nt][1], 1);
            float p2 = __shfl_xor_sync(0xffffffffu, d[nt][2], 1);
            float p3 = __shfl_xor_sync(0xffffffffu, d[nt][3], 1);
            float gi, gf, gc, go;
            if (!(lane & 1)) { gi = d[nt][0]; gf = d[nt][1]; gc = p0; go = p1; }
            else             { gi = p2;       gf = p3;       gc = d[nt][2]; go = d[nt][3]; }
            float2 wi = wxbp[4 * jl + 0], wf = wxbp[4 * jl + 1];
            float2 wc = wxbp[4 * jl + 2], wo = wxbp[4 * jl + 3];
            float pi = gi + xv * wi.x + wi.y;
            float pf = gf + xv * wf.x + wf.y;
            float pc = gc + xv * wc.x + wc.y;
            float po = go + xv * wo.x + wo.y;
            const int idx = my_row * HDIM + nb * 8 + jl;
            float cold = g_c[idx];
            float ig = 1.f / (1.f + expf(-pi));
            float fg = 1.f / (1.f + expf(-pf));
            float cn = fg * cold + ig * tanhf(pc);
            float hn = po * tanhf(cn);   // no sigmoid on output gate
            g_c[idx] = cn;
            __nv_bfloat16 hi = __float2bfloat16(hn);
            ohi[idx] = hi;
            olo[idx] = __float2bfloat16(hn - __bfloat162float(hi));
        }

        // ---------------- grid sync ----------------
        if (t + 1 < SEQ) {
            __syncthreads();
            if (tid == 0) {
                unsigned* ctr = &g_sync_ctr;
                asm volatile("red.release.gpu.global.add.u32 [%0], %1;"
                             :: "l"(ctr), "r"(1u) : "memory");
                const unsigned target = (unsigned)NCTA * (unsigned)(t + 1);
                unsigned v;
                do {
                    asm volatile("ld.acquire.gpu.global.u32 %0, [%1];"
                                 : "=r"(v) : "l"(ctr) : "memory");
                } while (v < target);
            }
            __syncthreads();
        }
    }
}

// ---------------------------------------------------------------------------
__global__ void out_final(const float* __restrict__ Wout,
                          const float* __restrict__ bout,
                          float* __restrict__ out) {
    int gtid = blockIdx.x * 128 + threadIdx.x;
    int r = gtid >> 5, lane = gtid & 31;
    float s = 0.f;
    for (int k = lane; k < HDIM; k += 32) {
        float h = __bfloat162float(g_hhi[0][r * HDIM + k]) +
                  __bfloat162float(g_hlo[0][r * HDIM + k]);
        s += h * Wout[k];
    }
#pragma unroll
    for (int o = 16; o; o >>= 1) s += __shfl_xor_sync(0xffffffffu, s, o);
    if (lane == 0) out[r] = s + bout[0];
}

// ---------------------------------------------------------------------------
extern "C" void kernel_launch(void* const* d_in, const int* in_sizes, int n_in,
                              void* d_out, int out_size) {
    (void)in_sizes; (void)n_in; (void)out_size;
    const float* x    = (const float*)d_in[0];
    const float* h0   = (const float*)d_in[1];
    const float* c0   = (const float*)d_in[2];
    const float* Wi   = (const float*)d_in[3];
    const float* bi   = (const float*)d_in[4];
    const float* Wf   = (const float*)d_in[5];
    const float* bf   = (const float*)d_in[6];
    const float* Wc   = (const float*)d_in[7];
    const float* bc   = (const float*)d_in[8];
    const float* Wo   = (const float*)d_in[9];
    const float* bo   = (const float*)d_in[10];
    const float* Wout = (const float*)d_in[11];
    const float* bout = (const float*)d_in[12];
    float* out = (float*)d_out;

    static int configured = 0;
    if (!configured) {
        cudaFuncSetAttribute(lstm_persistent,
                             cudaFuncAttributeMaxDynamicSharedMemorySize, SMEM_TOTAL);
        configured = 1;
    }

    init_state<<<(ROWS * HDIM + 255) / 256, 256>>>(h0, c0);
    repack<<<(NCTA * NCHUNK * 2048 + 255) / 256, 256>>>(Wi, Wf, Wc, Wo, bi, bf, bc, bo);
    lstm_persistent<<<NCTA, 256, SMEM_TOTAL>>>(x);
    out_final<<<32, 128>>>(Wout, bout, out);
}